// round 5
// baseline (speedup 1.0000x reference)
#include <cuda_runtime.h>
#include <cstdint>

// FP8 E4M3 bit-plane multiply -> exact FP32 bit-plane.
// Per element: 8 input bits (A) x 8 input bits (B) -> 32 output bits, all as 0/1 floats.
//
// Strategy: 1 thread = 1 element. Pack the 8 bit-plane floats into a byte
// (a 0/1 float is 0x3F800000 or 0x0, so bit = u >> 23 & 1), run the exact
// FP8*FP8->FP32 circuit in integer registers producing the 32-bit FP32 word,
// then use warp shuffles to emit warp-coalesced float4 stores (each STG.128
// covers 512B contiguous per warp).

__device__ __forceinline__ uint32_t pack_byte(float4 lo, float4 hi) {
    // lo = {s, e3, e2, e1}, hi = {e0, m2, m1, m0}; result bit7=s .. bit0=m0.
    uint32_t v;
    v  = (__float_as_uint(lo.x) >> 16) & 0x80u;  // s  -> bit 7
    v |= (__float_as_uint(lo.y) >> 17) & 0x40u;  // e3 -> bit 6
    v |= (__float_as_uint(lo.z) >> 18) & 0x20u;  // e2 -> bit 5
    v |= (__float_as_uint(lo.w) >> 19) & 0x10u;  // e1 -> bit 4
    v |= (__float_as_uint(hi.x) >> 20) & 0x08u;  // e0 -> bit 3
    v |= (__float_as_uint(hi.y) >> 21) & 0x04u;  // m2 -> bit 2
    v |= (__float_as_uint(hi.z) >> 22) & 0x02u;  // m1 -> bit 1
    v |= (__float_as_uint(hi.w) >> 23) & 0x01u;  // m0 -> bit 0
    return v;
}

// Decode packed FP8 byte -> sign, 4-bit significand (leading 1 at bit 3, or 0),
// biased FP32 exponent. nz folded in: frac==0 iff value is zero.
__device__ __forceinline__ void dec_fp8(uint32_t v, uint32_t& s, uint32_t& frac, int& exp) {
    s = v >> 7;
    uint32_t e = (v >> 3) & 15u;
    uint32_t m = v & 7u;
    // subnormal path (e==0): normalize leading one to bit 3.
    int p = 31 - __clz(m | 1u);           // m=0 -> p=0 -> frac stays 0
    uint32_t frac_sub = m << (3 - p);
    int exp_sub = 118 + p;
    frac = e ? (m + 8u) : frac_sub;
    exp  = e ? (int)e + 120 : exp_sub;
}

__global__ void __launch_bounds__(256, 8)
spike_fp8_mul_kernel(const float4* __restrict__ A4,
                     const float4* __restrict__ B4,
                     float4* __restrict__ O4,
                     int n_elem) {
    const int tid  = blockIdx.x * blockDim.x + threadIdx.x;
    const int lane = threadIdx.x & 31;
    const int eb   = tid - lane;          // warp's base element
    const int elem = tid;

    uint32_t word = 0u;
    if (elem < n_elem) {
        const float4 al = A4[(size_t)elem * 2 + 0];
        const float4 ah = A4[(size_t)elem * 2 + 1];
        const float4 bl = B4[(size_t)elem * 2 + 0];
        const float4 bh = B4[(size_t)elem * 2 + 1];

        const uint32_t va = pack_byte(al, ah);
        const uint32_t vb = pack_byte(bl, bh);

        uint32_t sa, fa; int ea;
        uint32_t sb, fb; int ebx;
        dec_fp8(va, sa, fa, ea);
        dec_fp8(vb, sb, fb, ebx);

        const uint32_t p     = fa * fb;        // [64, 225] when both nonzero
        const uint32_t carry = p >> 7;         // leading one at bit 7 vs bit 6
        const uint32_t pn    = p << (1u - carry); // normalize leading one to bit 7
        const int      eo    = ea + ebx - 127 + (int)carry;

        uint32_t body = ((uint32_t)eo << 23) | ((pn & 0x7Fu) << 16);
        const bool nz = ((va & 0x7Fu) != 0u) & ((vb & 0x7Fu) != 0u);
        word = ((sa ^ sb) << 31) | (nz ? body : 0u);
    }

    // Warp-coalesced output: iteration k writes float4 index eb*8 + k*32 + lane.
    // That float4 belongs to element eb + k*4 + lane/8, bits [4*(lane&7), +4).
    const uint32_t j0 = (uint32_t)(lane & 7) * 4u;
#pragma unroll
    for (int k = 0; k < 8; ++k) {
        const uint32_t w  = __shfl_sync(0xFFFFFFFFu, word, k * 4 + (lane >> 3));
        const uint32_t ws = w << j0;     // target bit group now at bits 31..28
        float4 f;
        f.x = __uint_as_float(((int)(ws      ) >> 31) & 0x3F800000);
        f.y = __uint_as_float(((int)(ws << 1) >> 31) & 0x3F800000);
        f.z = __uint_as_float(((int)(ws << 2) >> 31) & 0x3F800000);
        f.w = __uint_as_float(((int)(ws << 3) >> 31) & 0x3F800000);
        const int src_elem = eb + k * 4 + (lane >> 3);
        if (src_elem < n_elem)
            O4[(size_t)eb * 8 + (size_t)k * 32 + lane] = f;
    }
}

extern "C" void kernel_launch(void* const* d_in, const int* in_sizes, int n_in,
                              void* d_out, int out_size) {
    const float4* A4 = (const float4*)d_in[0];
    const float4* B4 = (const float4*)d_in[1];
    float4* O4 = (float4*)d_out;

    const int n_elem = in_sizes[0] / 8;   // 1024*4096 = 4,194,304
    const int threads = 256;
    const int blocks  = (n_elem + threads - 1) / threads;

    spike_fp8_mul_kernel<<<blocks, threads>>>(A4, B4, O4, n_elem);
}